// round 11
// baseline (speedup 1.0000x reference)
#include <cuda_runtime.h>
#include <cuda_bf16.h>
#include <cstdint>

#define TOK   200704            // 64*56*56 tokens
#define CDIM  256
#define QKVN  768
#define WS    7
#define WT    49
#define NHEAD 8
#define HDIM  32

// ------------------------- scratch (device globals) -------------------------
__device__ float          g_qkv[154140672];          // [TOK][768] fp32
__device__ __nv_bfloat16  g_xh [51380224];           // [TOK][256] x hi
__device__ __nv_bfloat16  g_xl [51380224];           // [TOK][256] x lo
__device__ __nv_bfloat16  g_ah [51380224];           // attn out hi
__device__ __nv_bfloat16  g_al [51380224];           // attn out lo
__device__ __nv_bfloat16  g_wqT_h[196608];           // WqkvT [768][256] K-major
__device__ __nv_bfloat16  g_wqT_l[196608];
__device__ __nv_bfloat16  g_woT_h[65536];            // WoutT [256][256] K-major
__device__ __nv_bfloat16  g_woT_l[65536];

// ------------------------- helpers -------------------------
__device__ __forceinline__ uint32_t smem_u32(const void* p) {
    uint32_t a;
    asm("{ .reg .u64 t; cvta.to.shared.u64 t, %1; cvt.u32.u64 %0, t; }" : "=r"(a) : "l"(p));
    return a;
}
#define CP_ASYNC16(dst, src) \
    asm volatile("cp.async.cg.shared.global [%0], [%1], 16;\n" :: "r"(dst), "l"(src))
#define CP_COMMIT() asm volatile("cp.async.commit_group;\n" ::: "memory")

__device__ __forceinline__ void ldsm4(uint32_t addr, uint32_t* r) {
    asm volatile("ldmatrix.sync.aligned.m8n8.x4.shared.b16 {%0,%1,%2,%3}, [%4];"
        : "=r"(r[0]), "=r"(r[1]), "=r"(r[2]), "=r"(r[3]) : "r"(addr));
}
__device__ __forceinline__ void mma16816(float* c, const uint32_t* a, const uint32_t* b) {
    asm volatile(
        "mma.sync.aligned.m16n8k16.row.col.f32.bf16.bf16.f32 "
        "{%0,%1,%2,%3}, {%4,%5,%6,%7}, {%8,%9}, {%0,%1,%2,%3};"
        : "+f"(c[0]), "+f"(c[1]), "+f"(c[2]), "+f"(c[3])
        : "r"(a[0]), "r"(a[1]), "r"(a[2]), "r"(a[3]), "r"(b[0]), "r"(b[1]));
}
// SW64 swizzle for 64B rows: conflict-free ldmatrix over 8 consecutive rows
__device__ __forceinline__ uint32_t sw64(uint32_t row, uint32_t kb) {
    uint32_t off = (row << 6) + kb;
    return off ^ ((off >> 3) & 0x30);
}
__device__ __forceinline__ void split2(float v, __nv_bfloat16& h, __nv_bfloat16& l) {
    h = __float2bfloat16_rn(v);
    l = __float2bfloat16_rn(v - __bfloat162float(h));
}

// ------------------------- P0: split kernels -------------------------
__global__ void split_x_kernel(const float* __restrict__ x) {
    size_t n4 = (size_t)TOK * CDIM / 4;
    for (size_t i = (size_t)blockIdx.x * blockDim.x + threadIdx.x; i < n4;
         i += (size_t)gridDim.x * blockDim.x) {
        float4 v = ((const float4*)x)[i];
        __nv_bfloat16 h0,h1,h2,h3,l0,l1,l2,l3;
        split2(v.x,h0,l0); split2(v.y,h1,l1); split2(v.z,h2,l2); split2(v.w,h3,l3);
        ((__nv_bfloat162*)g_xh)[2*i]   = __nv_bfloat162(h0,h1);
        ((__nv_bfloat162*)g_xh)[2*i+1] = __nv_bfloat162(h2,h3);
        ((__nv_bfloat162*)g_xl)[2*i]   = __nv_bfloat162(l0,l1);
        ((__nv_bfloat162*)g_xl)[2*i+1] = __nv_bfloat162(l2,l3);
    }
}
__global__ void split_wT_kernel(const float* __restrict__ w,
                                __nv_bfloat16* __restrict__ oh,
                                __nv_bfloat16* __restrict__ ol, int N) {
    int idx = blockIdx.x * blockDim.x + threadIdx.x;
    if (idx >= N * CDIM) return;
    int n = idx >> 8, k = idx & 255;
    __nv_bfloat16 h, l;
    split2(w[(size_t)k * N + n], h, l);
    oh[(size_t)n * CDIM + k] = h;
    ol[(size_t)n * CDIM + k] = l;
}

// ------------------------- split-bf16 GEMM on mma.sync -------------------------
// C[M,N] = A[M,256] @ B[N,256]^T, tiles 128x128, K-chunks of 32, 5-stage cp.async.
#define BM 128
#define BN 128
#define BK 32
#define NKCH (CDIM / BK)        // 8 chunks
#define NSTAGE 5
#define AH_OFF 0
#define AL_OFF 8192
#define BH_OFF 16384
#define BL_OFF 24576
#define STAGE_BYTES 32768
#define GEMM_SMEM (NSTAGE * STAGE_BYTES)

__device__ __forceinline__ void load_chunk(uint32_t sb, int c,
    const __nv_bfloat16* __restrict__ Ah, const __nv_bfloat16* __restrict__ Al,
    const __nv_bfloat16* __restrict__ Bh, const __nv_bfloat16* __restrict__ Bl,
    int m0, int n0, int tid)
{
    #pragma unroll
    for (int i = 0; i < 2; ++i) {
        int t = tid + i * 256, r = t >> 2, seg = (t & 3) * 16;   // row, byte-col
        uint32_t dst = sb + sw64((uint32_t)r, (uint32_t)seg);
        size_t ga = (size_t)(m0 + r) * CDIM + c * BK + (seg >> 1);
        CP_ASYNC16(dst + AH_OFF, Ah + ga);
        CP_ASYNC16(dst + AL_OFF, Al + ga);
        size_t gb = (size_t)(n0 + r) * CDIM + c * BK + (seg >> 1);
        CP_ASYNC16(dst + BH_OFF, Bh + gb);
        CP_ASYNC16(dst + BL_OFF, Bl + gb);
    }
    CP_COMMIT();
}

__global__ __launch_bounds__(256, 1)
void gemm_split_kernel(const __nv_bfloat16* __restrict__ Ah, const __nv_bfloat16* __restrict__ Al,
                       const __nv_bfloat16* __restrict__ Bh, const __nv_bfloat16* __restrict__ Bl,
                       const float* __restrict__ bias, float* __restrict__ outp, int out_ld)
{
    extern __shared__ __align__(1024) char smem[];
    const uint32_t smb = smem_u32(smem);
    const int tid  = threadIdx.x;
    const int lane = tid & 31, wid = tid >> 5;
    const int wm = wid & 3, wn = wid >> 2;              // 4 M-warps x 2 N-warps
    const int n0 = blockIdx.x * BN;
    const int m0 = blockIdx.y * BM;

    const int li = lane & 7, lg = lane >> 3;
    const int aRowOff = ((lg & 1) << 3) + li;
    const int aKoff   = (lg >> 1) << 4;
    const int bRowOff = ((lg >> 1) << 3) + li;
    const int bKoff   = (lg & 1) << 4;

    float acc[2][8][4];
    #pragma unroll
    for (int a = 0; a < 2; ++a)
        #pragma unroll
        for (int b = 0; b < 8; ++b)
            #pragma unroll
            for (int cc = 0; cc < 4; ++cc) acc[a][b][cc] = 0.f;

    // prologue: 4 chunks in flight
    load_chunk(smb + 0 * STAGE_BYTES, 0, Ah, Al, Bh, Bl, m0, n0, tid);
    load_chunk(smb + 1 * STAGE_BYTES, 1, Ah, Al, Bh, Bl, m0, n0, tid);
    load_chunk(smb + 2 * STAGE_BYTES, 2, Ah, Al, Bh, Bl, m0, n0, tid);
    load_chunk(smb + 3 * STAGE_BYTES, 3, Ah, Al, Bh, Bl, m0, n0, tid);

    #pragma unroll 1
    for (int c = 0; c < NKCH; ++c) {
        if (c < 5)      asm volatile("cp.async.wait_group 3;\n" ::: "memory");
        else if (c == 5) asm volatile("cp.async.wait_group 2;\n" ::: "memory");
        else if (c == 6) asm volatile("cp.async.wait_group 1;\n" ::: "memory");
        else             asm volatile("cp.async.wait_group 0;\n" ::: "memory");
        __syncthreads();
        const uint32_t sb = smb + (uint32_t)(c % NSTAGE) * STAGE_BYTES;

        #pragma unroll
        for (int s = 0; s < 2; ++s) {                    // 2 x k16 steps
            const uint32_t kbA = (uint32_t)(s * 32 + aKoff);
            const uint32_t kbB = (uint32_t)(s * 32 + bKoff);
            uint32_t ah[2][4], al[2][4];
            #pragma unroll
            for (int mt = 0; mt < 2; ++mt) {
                const uint32_t arow = (uint32_t)(wm * 32 + mt * 16 + aRowOff);
                const uint32_t sw = sw64(arow, kbA);
                ldsm4(sb + AH_OFF + sw, ah[mt]);
                ldsm4(sb + AL_OFF + sw, al[mt]);
            }
            uint32_t bh[4][4], bl[4][4];
            #pragma unroll
            for (int nt = 0; nt < 4; ++nt) {
                const uint32_t brow = (uint32_t)(wn * 64 + nt * 16 + bRowOff);
                const uint32_t sw = sw64(brow, kbB);
                ldsm4(sb + BH_OFF + sw, bh[nt]);
                ldsm4(sb + BL_OFF + sw, bl[nt]);
            }
            #pragma unroll
            for (int mt = 0; mt < 2; ++mt)
                #pragma unroll
                for (int nt = 0; nt < 4; ++nt) {
                    mma16816(acc[mt][nt*2],   ah[mt], &bh[nt][0]);
                    mma16816(acc[mt][nt*2],   ah[mt], &bl[nt][0]);
                    mma16816(acc[mt][nt*2],   al[mt], &bh[nt][0]);
                    mma16816(acc[mt][nt*2+1], ah[mt], &bh[nt][2]);
                    mma16816(acc[mt][nt*2+1], ah[mt], &bl[nt][2]);
                    mma16816(acc[mt][nt*2+1], al[mt], &bh[nt][2]);
                }
        }
        if (c + 4 < NKCH)
            load_chunk(smb + (uint32_t)((c + 4) % NSTAGE) * STAGE_BYTES, c + 4,
                       Ah, Al, Bh, Bl, m0, n0, tid);
    }

    #pragma unroll
    for (int mt = 0; mt < 2; ++mt) {
        const int row = m0 + wm * 32 + mt * 16 + (lane >> 2);
        #pragma unroll
        for (int nt = 0; nt < 8; ++nt) {
            const int col = n0 + wn * 64 + nt * 8 + 2 * (lane & 3);
            const float b0 = __ldg(bias + col), b1 = __ldg(bias + col + 1);
            float2 v0 = make_float2(acc[mt][nt][0] + b0, acc[mt][nt][1] + b1);
            float2 v1 = make_float2(acc[mt][nt][2] + b0, acc[mt][nt][3] + b1);
            *(float2*)(outp + (size_t)row * out_ld + col)       = v0;
            *(float2*)(outp + (size_t)(row + 8) * out_ld + col) = v1;
        }
    }
}

// ------------------------- K2: windowed attention (4 heads/CTA, 2 warps/head, dual q-token) -------------------------
#define TP 52
#define HPC 4
#define ATT_SMEM ((128*TP*2 + HPC*WT*HDIM + 169 + 7) * 4)

__global__ __launch_bounds__(256, 2)
void attn_kernel(const float* __restrict__ pos)
{
    extern __shared__ float smf[];
    float* qT    = smf;                          // [128][52]
    float* kT    = qT + 128*TP;                  // [128][52]
    float* v_s   = kT + 128*TP;                  // [4][49][32]
    float* pos_s = v_s + HPC*WT*HDIM;            // [169]

    const int tid = threadIdx.x;
    const int win = blockIdx.x >> 1;
    const int hh  = blockIdx.x & 1;
    const int b = win >> 6, wi = (win >> 3) & 7, wj = win & 7;
    const int base_tok = b * 3136 + (wi * WS) * 56 + wj * WS;

    if (tid < 169) pos_s[tid] = pos[tid];

    // load phase: threads 0-127 load q+v, threads 128-255 load k; zero pad cols 49..51
    {
        const int cl = tid & 127;
        const bool isK = tid >= 128;
        #pragma unroll 7
        for (int t = 0; t < WT; ++t) {
            const int row = base_tok + (t / WS) * 56 + (t % WS);
            const float* rp = g_qkv + (size_t)row * QKVN;
            if (!isK) {
                qT[cl * TP + t] = rp[hh * 128 + cl];
                v_s[((cl >> 5) * WT + t) * HDIM + (cl & 31)] = rp[512 + hh * 128 + cl];
            } else {
                kT[cl * TP + t] = rp[256 + hh * 128 + cl];
            }
        }
        float* padp = (tid < 128) ? (qT + cl * TP) : (kT + cl * TP);
        padp[49] = 0.f; padp[50] = 0.f; padp[51] = 0.f;
    }
    __syncthreads();

    {
        const int lane = tid & 31;
        const int wid  = tid >> 5;
        const int hl   = wid >> 1;
        const int half = wid & 1;
        const int qs = half ? 25 : 0;
        const int qe = half ? WT : 25;

        const float* qTh = qT + hl * HDIM * TP;
        const float* kTh = kT + hl * HDIM * TP;
        const float* vh  = v_s + hl * WT * HDIM;

        const int j1 = lane;
        const bool has2 = (lane < 17);
        const int j2 = has2 ? lane + 32 : 0;

        float kk1[HDIM], kk2[HDIM];
        #pragma unroll
        for (int dd = 0; dd < HDIM; ++dd) {
            kk1[dd] = kTh[dd * TP + j1];
            kk2[dd] = kTh[dd * TP + j2];
        }
        const int ij1 = j1 / WS + j1 % WS;
        const int ij2 = j2 / WS + j2 % WS;
        const float SQ = 5.6568542494923806f;    // sqrt(32), reference multiplies

        const int ch = hh * 128 + hl * HDIM + lane;

        for (int qt = qs; qt < qe; qt += 2) {
            const bool two = (qt + 1 < qe);
            // ---- dual QK dot products ----
            float sa0 = 0.f, sa1 = 0.f, sb0 = 0.f, sb1 = 0.f;
            #pragma unroll
            for (int dd = 0; dd < HDIM; ++dd) {
                const float qa = qTh[dd * TP + qt];
                const float qb = qTh[dd * TP + qt + 1];   // col<=50, zero-padded
                sa0 = fmaf(qa, kk1[dd], sa0);
                sa1 = fmaf(qa, kk2[dd], sa1);
                sb0 = fmaf(qb, kk1[dd], sb0);
                sb1 = fmaf(qb, kk2[dd], sb1);
            }
            const int iqa = (qt / WS + qt % WS) * 13;
            const int iqb = ((qt + 1) / WS + (qt + 1) % WS) * 13;
            sa0 = sa0 * SQ + pos_s[iqa + ij1];
            sa1 = has2 ? (sa1 * SQ + pos_s[iqa + ij2]) : -1e30f;
            sb0 = sb0 * SQ + pos_s[iqb + ij1];
            sb1 = has2 ? (sb1 * SQ + pos_s[iqb + ij2]) : -1e30f;

            // ---- interleaved softmax reductions (independent chains overlap) ----
            float ma = fmaxf(sa0, sa1);
            float mb = fmaxf(sb0, sb1);
            #pragma unroll
            for (int o = 16; o; o >>= 1) {
                ma = fmaxf(ma, __shfl_xor_sync(0xFFFFFFFFu, ma, o));
                mb = fmaxf(mb, __shfl_xor_sync(0xFFFFFFFFu, mb, o));
            }
            const float ea0 = __expf(sa0 - ma);
            const float ea1 = has2 ? __expf(sa1 - ma) : 0.f;
            const float eb0 = __expf(sb0 - mb);
            const float eb1 = has2 ? __expf(sb1 - mb) : 0.f;
            float suma = ea0 + ea1;
            float sumb = eb0 + eb1;
            #pragma unroll
            for (int o = 16; o; o >>= 1) {
                suma += __shfl_xor_sync(0xFFFFFFFFu, suma, o);
                sumb += __shfl_xor_sync(0xFFFFFFFFu, sumb, o);
            }
            const float inva = __fdividef(1.f, suma);
            const float invb = __fdividef(1.f, sumb);
            const float pa0 = ea0 * inva, pa1 = ea1 * inva;
            const float pb0 = eb0 * invb, pb1 = eb1 * invb;

            // ---- shared-v PV ----
            float oa = 0.f, ob = 0.f;
            #pragma unroll
            for (int j = 0; j < 32; ++j) {
                const float vj = vh[j * HDIM + lane];
                oa = fmaf(__shfl_sync(0xFFFFFFFFu, pa0, j), vj, oa);
                ob = fmaf(__shfl_sync(0xFFFFFFFFu, pb0, j), vj, ob);
            }
            #pragma unroll
            for (int j = 0; j < 17; ++j) {
                const float vj = vh[(j + 32) * HDIM + lane];
                oa = fmaf(__shfl_sync(0xFFFFFFFFu, pa1, j), vj, oa);
                ob = fmaf(__shfl_sync(0xFFFFFFFFu, pb1, j), vj, ob);
            }

            {
                const int row = base_tok + (qt / WS) * 56 + (qt % WS);
                __nv_bfloat16 oh, ol;
                split2(oa, oh, ol);
                g_ah[(size_t)row * CDIM + ch] = oh;
                g_al[(size_t)row * CDIM + ch] = ol;
            }
            if (two) {
                const int row = base_tok + ((qt + 1) / WS) * 56 + ((qt + 1) % WS);
                __nv_bfloat16 oh, ol;
                split2(ob, oh, ol);
                g_ah[(size_t)row * CDIM + ch] = oh;
                g_al[(size_t)row * CDIM + ch] = ol;
            }
        }
    }
}

// ------------------------- host launcher -------------------------
extern "C" void kernel_launch(void* const* d_in, const int* in_sizes, int n_in,
                              void* d_out, int out_size)
{
    const float* x     = (const float*)d_in[0];
    const float* pos   = (const float*)d_in[1];
    const float* w_qkv = (const float*)d_in[2];
    const float* b_qkv = (const float*)d_in[3];
    const float* w_out = (const float*)d_in[4];
    const float* b_out = (const float*)d_in[5];
    float* out = (float*)d_out;

    void *p_qkv, *p_xh, *p_xl, *p_ah, *p_al, *p_wqh, *p_wql, *p_woh, *p_wol;
    cudaGetSymbolAddress(&p_qkv, g_qkv);
    cudaGetSymbolAddress(&p_xh,  g_xh);
    cudaGetSymbolAddress(&p_xl,  g_xl);
    cudaGetSymbolAddress(&p_ah,  g_ah);
    cudaGetSymbolAddress(&p_al,  g_al);
    cudaGetSymbolAddress(&p_wqh, g_wqT_h);
    cudaGetSymbolAddress(&p_wql, g_wqT_l);
    cudaGetSymbolAddress(&p_woh, g_woT_h);
    cudaGetSymbolAddress(&p_wol, g_woT_l);

    cudaFuncSetAttribute(gemm_split_kernel, cudaFuncAttributeMaxDynamicSharedMemorySize, GEMM_SMEM);
    cudaFuncSetAttribute(attn_kernel,       cudaFuncAttributeMaxDynamicSharedMemorySize, ATT_SMEM);

    // P0: splits
    split_x_kernel<<<2048, 256>>>(x);
    split_wT_kernel<<<(QKVN * CDIM) / 256, 256>>>(w_qkv, (__nv_bfloat16*)p_wqh, (__nv_bfloat16*)p_wql, QKVN);
    split_wT_kernel<<<(CDIM * CDIM) / 256, 256>>>(w_out, (__nv_bfloat16*)p_woh, (__nv_bfloat16*)p_wol, CDIM);

    // K1: QKV GEMM  [200704 x 768]
    gemm_split_kernel<<<dim3(QKVN / BN, TOK / BM), 256, GEMM_SMEM>>>(
        (const __nv_bfloat16*)p_xh, (const __nv_bfloat16*)p_xl,
        (const __nv_bfloat16*)p_wqh, (const __nv_bfloat16*)p_wql,
        b_qkv, (float*)p_qkv, QKVN);

    // K2: windowed attention (2 CTAs per window)
    attn_kernel<<<8192, 256, ATT_SMEM>>>(pos);

    // K3: output projection  [200704 x 256]
    gemm_split_kernel<<<dim3(CDIM / BN, TOK / BM), 256, GEMM_SMEM>>>(
        (const __nv_bfloat16*)p_ah, (const __nv_bfloat16*)p_al,
        (const __nv_bfloat16*)p_woh, (const __nv_bfloat16*)p_wol,
        b_out, out, CDIM);
}

// round 12
// speedup vs baseline: 1.4931x; 1.4931x over previous
#include <cuda_runtime.h>
#include <cuda_bf16.h>
#include <cstdint>

#define TOK   200704            // 64*56*56 tokens
#define CDIM  256
#define QKVN  768
#define WS    7
#define WT    49
#define NHEAD 8
#define HDIM  32

// ------------------------- scratch (device globals) -------------------------
__device__ float          g_qkv[154140672];          // [TOK][768] fp32
__device__ __nv_bfloat16  g_xh [51380224];           // [TOK][256] x hi
__device__ __nv_bfloat16  g_xl [51380224];           // [TOK][256] x lo
__device__ __nv_bfloat16  g_ah [51380224];           // attn out hi
__device__ __nv_bfloat16  g_al [51380224];           // attn out lo
__device__ __nv_bfloat16  g_wqT_h[196608];           // WqkvT [768][256] K-major
__device__ __nv_bfloat16  g_wqT_l[196608];
__device__ __nv_bfloat16  g_woT_h[65536];            // WoutT [256][256] K-major
__device__ __nv_bfloat16  g_woT_l[65536];

// ------------------------- helpers -------------------------
__device__ __forceinline__ uint32_t smem_u32(const void* p) {
    uint32_t a;
    asm("{ .reg .u64 t; cvta.to.shared.u64 t, %1; cvt.u32.u64 %0, t; }" : "=r"(a) : "l"(p));
    return a;
}
#define CP_ASYNC16(dst, src) \
    asm volatile("cp.async.cg.shared.global [%0], [%1], 16;\n" :: "r"(dst), "l"(src))
#define CP_COMMIT() asm volatile("cp.async.commit_group;\n" ::: "memory")

__device__ __forceinline__ void ldsm4(uint32_t addr, uint32_t* r) {
    asm volatile("ldmatrix.sync.aligned.m8n8.x4.shared.b16 {%0,%1,%2,%3}, [%4];"
        : "=r"(r[0]), "=r"(r[1]), "=r"(r[2]), "=r"(r[3]) : "r"(addr));
}
__device__ __forceinline__ void mma16816(float* c, const uint32_t* a, const uint32_t* b) {
    asm volatile(
        "mma.sync.aligned.m16n8k16.row.col.f32.bf16.bf16.f32 "
        "{%0,%1,%2,%3}, {%4,%5,%6,%7}, {%8,%9}, {%0,%1,%2,%3};"
        : "+f"(c[0]), "+f"(c[1]), "+f"(c[2]), "+f"(c[3])
        : "r"(a[0]), "r"(a[1]), "r"(a[2]), "r"(a[3]), "r"(b[0]), "r"(b[1]));
}
__device__ __forceinline__ uint32_t sw128(uint32_t row, uint32_t kb) {
    uint32_t off = (row << 7) + kb;
    return off ^ ((off >> 3) & 0x70);
}
__device__ __forceinline__ void split2(float v, __nv_bfloat16& h, __nv_bfloat16& l) {
    h = __float2bfloat16_rn(v);
    l = __float2bfloat16_rn(v - __bfloat162float(h));
}

// ------------------------- P0: split kernels -------------------------
__global__ void split_x_kernel(const float* __restrict__ x) {
    size_t n4 = (size_t)TOK * CDIM / 4;
    for (size_t i = (size_t)blockIdx.x * blockDim.x + threadIdx.x; i < n4;
         i += (size_t)gridDim.x * blockDim.x) {
        float4 v = ((const float4*)x)[i];
        __nv_bfloat16 h0,h1,h2,h3,l0,l1,l2,l3;
        split2(v.x,h0,l0); split2(v.y,h1,l1); split2(v.z,h2,l2); split2(v.w,h3,l3);
        ((__nv_bfloat162*)g_xh)[2*i]   = __nv_bfloat162(h0,h1);
        ((__nv_bfloat162*)g_xh)[2*i+1] = __nv_bfloat162(h2,h3);
        ((__nv_bfloat162*)g_xl)[2*i]   = __nv_bfloat162(l0,l1);
        ((__nv_bfloat162*)g_xl)[2*i+1] = __nv_bfloat162(l2,l3);
    }
}
__global__ void split_wT_kernel(const float* __restrict__ w,
                                __nv_bfloat16* __restrict__ oh,
                                __nv_bfloat16* __restrict__ ol, int N) {
    int idx = blockIdx.x * blockDim.x + threadIdx.x;
    if (idx >= N * CDIM) return;
    int n = idx >> 8, k = idx & 255;
    __nv_bfloat16 h, l;
    split2(w[(size_t)k * N + n], h, l);
    oh[(size_t)n * CDIM + k] = h;
    ol[(size_t)n * CDIM + k] = l;
}

// ------------------------- split-bf16 GEMM on mma.sync (R8 proven config) -------------------------
#define BM 128
#define BN 128
#define BK 64
#define NSTAGE 3
#define AH_OFF 0
#define AL_OFF 16384
#define BH_OFF 32768
#define BL_OFF 49152
#define STAGE_BYTES 65536
#define GEMM_SMEM (NSTAGE * STAGE_BYTES)

__device__ __forceinline__ void load_chunk(uint32_t sb, int c,
    const __nv_bfloat16* __restrict__ Ah, const __nv_bfloat16* __restrict__ Al,
    const __nv_bfloat16* __restrict__ Bh, const __nv_bfloat16* __restrict__ Bl,
    int m0, int n0, int tid)
{
    #pragma unroll
    for (int i = 0; i < 4; ++i) {
        int t = tid + i * 256, r = t >> 3, seg = t & 7;
        uint32_t dst = sb + sw128(r, seg * 16);
        size_t ga = (size_t)(m0 + r) * CDIM + c * BK + seg * 8;
        CP_ASYNC16(dst + AH_OFF, Ah + ga);
        CP_ASYNC16(dst + AL_OFF, Al + ga);
        size_t gb = (size_t)(n0 + r) * CDIM + c * BK + seg * 8;
        CP_ASYNC16(dst + BH_OFF, Bh + gb);
        CP_ASYNC16(dst + BL_OFF, Bl + gb);
    }
    CP_COMMIT();
}

__global__ __launch_bounds__(256, 1)
void gemm_split_kernel(const __nv_bfloat16* __restrict__ Ah, const __nv_bfloat16* __restrict__ Al,
                       const __nv_bfloat16* __restrict__ Bh, const __nv_bfloat16* __restrict__ Bl,
                       const float* __restrict__ bias, float* __restrict__ outp, int out_ld)
{
    extern __shared__ __align__(1024) char smem[];
    const uint32_t smb = smem_u32(smem);
    const int tid  = threadIdx.x;
    const int lane = tid & 31, wid = tid >> 5;
    const int wm = wid & 3, wn = wid >> 2;              // 4 M-warps x 2 N-warps
    const int n0 = blockIdx.x * BN;
    const int m0 = blockIdx.y * BM;

    const int li = lane & 7, lg = lane >> 3;
    const int aRowOff = ((lg & 1) << 3) + li;
    const int aKoff   = (lg >> 1) << 4;
    const int bRowOff = ((lg >> 1) << 3) + li;
    const int bKoff   = (lg & 1) << 4;

    float acc[2][8][4];
    #pragma unroll
    for (int a = 0; a < 2; ++a)
        #pragma unroll
        for (int b = 0; b < 8; ++b)
            #pragma unroll
            for (int cc = 0; cc < 4; ++cc) acc[a][b][cc] = 0.f;

    load_chunk(smb + 0 * STAGE_BYTES, 0, Ah, Al, Bh, Bl, m0, n0, tid);
    load_chunk(smb + 1 * STAGE_BYTES, 1, Ah, Al, Bh, Bl, m0, n0, tid);

    #pragma unroll 1
    for (int c = 0; c < 4; ++c) {
        if (c < 3) asm volatile("cp.async.wait_group 1;\n" ::: "memory");
        else       asm volatile("cp.async.wait_group 0;\n" ::: "memory");
        __syncthreads();
        const uint32_t sb = smb + (uint32_t)(c % NSTAGE) * STAGE_BYTES;

        #pragma unroll
        for (int s = 0; s < 4; ++s) {
            const uint32_t kbA = (uint32_t)(s * 32 + aKoff);
            const uint32_t kbB = (uint32_t)(s * 32 + bKoff);
            uint32_t ah[2][4], al[2][4];
            #pragma unroll
            for (int mt = 0; mt < 2; ++mt) {
                const uint32_t arow = (uint32_t)(wm * 32 + mt * 16 + aRowOff);
                const uint32_t sw = sw128(arow, kbA);
                ldsm4(sb + AH_OFF + sw, ah[mt]);
                ldsm4(sb + AL_OFF + sw, al[mt]);
            }
            uint32_t bh[4][4], bl[4][4];
            #pragma unroll
            for (int nt = 0; nt < 4; ++nt) {
                const uint32_t brow = (uint32_t)(wn * 64 + nt * 16 + bRowOff);
                const uint32_t sw = sw128(brow, kbB);
                ldsm4(sb + BH_OFF + sw, bh[nt]);
                ldsm4(sb + BL_OFF + sw, bl[nt]);
            }
            #pragma unroll
            for (int mt = 0; mt < 2; ++mt)
                #pragma unroll
                for (int nt = 0; nt < 4; ++nt) {
                    mma16816(acc[mt][nt*2],   ah[mt], &bh[nt][0]);
                    mma16816(acc[mt][nt*2],   ah[mt], &bl[nt][0]);
                    mma16816(acc[mt][nt*2],   al[mt], &bh[nt][0]);
                    mma16816(acc[mt][nt*2+1], ah[mt], &bh[nt][2]);
                    mma16816(acc[mt][nt*2+1], ah[mt], &bl[nt][2]);
                    mma16816(acc[mt][nt*2+1], al[mt], &bh[nt][2]);
                }
        }
        if (c + 2 < 4)
            load_chunk(smb + (uint32_t)((c + 2) % NSTAGE) * STAGE_BYTES, c + 2,
                       Ah, Al, Bh, Bl, m0, n0, tid);
    }

    #pragma unroll
    for (int mt = 0; mt < 2; ++mt) {
        const int row = m0 + wm * 32 + mt * 16 + (lane >> 2);
        #pragma unroll
        for (int nt = 0; nt < 8; ++nt) {
            const int col = n0 + wn * 64 + nt * 8 + 2 * (lane & 3);
            const float b0 = __ldg(bias + col), b1 = __ldg(bias + col + 1);
            float2 v0 = make_float2(acc[mt][nt][0] + b0, acc[mt][nt][1] + b1);
            float2 v1 = make_float2(acc[mt][nt][2] + b0, acc[mt][nt][3] + b1);
            *(float2*)(outp + (size_t)row * out_ld + col)       = v0;
            *(float2*)(outp + (size_t)(row + 8) * out_ld + col) = v1;
        }
    }
}

// ------------------------- K2: windowed attention (2 heads/CTA, 4 warps/head) -------------------------
#define TP 52
#define HPC 2                                    // heads per CTA
// smem: qT[64][52] + kT[64][52] + v[2][49][32] + pos[169]
#define ATT_SMEM ((64*TP*2 + HPC*WT*HDIM + 169 + 7) * 4)

__global__ __launch_bounds__(256, 2)
void attn_kernel(const float* __restrict__ pos)
{
    extern __shared__ float smf[];
    float* qT    = smf;                          // [64][52]
    float* kT    = qT + 64*TP;                   // [64][52]
    float* v_s   = kT + 64*TP;                   // [2][49][32]
    float* pos_s = v_s + HPC*WT*HDIM;            // [169]

    const int tid = threadIdx.x;
    const int win = blockIdx.x >> 2;
    const int hh  = blockIdx.x & 3;              // head-pair: heads hh*2, hh*2+1
    const int b = win >> 6, wi = (win >> 3) & 7, wj = win & 7;
    const int base_tok = b * 3136 + (wi * WS) * 56 + wj * WS;

    if (tid < 169) pos_s[tid] = pos[tid];

    // load phase: role = tid>>6: 0 -> q, 1 -> k, 2 -> v, 3 -> idle
    {
        const int cl   = tid & 63;               // local channel 0..63
        const int role = tid >> 6;
        if (role == 0) {
            #pragma unroll 7
            for (int t = 0; t < WT; ++t) {
                const int row = base_tok + (t / WS) * 56 + (t % WS);
                qT[cl * TP + t] = g_qkv[(size_t)row * QKVN + hh * 64 + cl];
            }
            qT[cl * TP + 49] = 0.f; qT[cl * TP + 50] = 0.f; qT[cl * TP + 51] = 0.f;
        } else if (role == 1) {
            #pragma unroll 7
            for (int t = 0; t < WT; ++t) {
                const int row = base_tok + (t / WS) * 56 + (t % WS);
                kT[cl * TP + t] = g_qkv[(size_t)row * QKVN + 256 + hh * 64 + cl];
            }
            kT[cl * TP + 49] = 0.f; kT[cl * TP + 50] = 0.f; kT[cl * TP + 51] = 0.f;
        } else if (role == 2) {
            #pragma unroll 7
            for (int t = 0; t < WT; ++t) {
                const int row = base_tok + (t / WS) * 56 + (t % WS);
                v_s[((cl >> 5) * WT + t) * HDIM + (cl & 31)] =
                    g_qkv[(size_t)row * QKVN + 512 + hh * 64 + cl];
            }
        }
    }
    __syncthreads();

    // compute: warp w -> head hl = w>>2 (0..1), quarter qtr = w&3 (tokens 13/13/13/10)
    {
        const int lane = tid & 31;
        const int wid  = tid >> 5;
        const int hl   = wid >> 2;
        const int qtr  = wid & 3;
        const int qs = qtr * 13;
        const int qe = (qtr == 3) ? WT : qs + 13;

        const float* qTh = qT + hl * HDIM * TP;
        const float* kTh = kT + hl * HDIM * TP;
        const float* vh  = v_s + hl * WT * HDIM;

        const int j1 = lane;
        const bool has2 = (lane < 17);
        const int j2 = has2 ? lane + 32 : 0;

        float kk1[HDIM], kk2[HDIM];
        #pragma unroll
        for (int dd = 0; dd < HDIM; ++dd) {
            kk1[dd] = kTh[dd * TP + j1];
            kk2[dd] = kTh[dd * TP + j2];
        }
        const int ij1 = j1 / WS + j1 % WS;
        const int ij2 = j2 / WS + j2 % WS;
        const float SQ = 5.6568542494923806f;    // sqrt(32), reference multiplies

        const int ch = hh * 64 + hl * HDIM + lane;    // global output channel

        for (int qt = qs; qt < qe; ++qt) {
            float s0 = 0.f, s1 = 0.f;
            #pragma unroll
            for (int dd = 0; dd < HDIM; ++dd) {
                const float qv = qTh[dd * TP + qt];
                s0 = fmaf(qv, kk1[dd], s0);
                s1 = fmaf(qv, kk2[dd], s1);
            }
            const int iq13 = (qt / WS + qt % WS) * 13;
            s0 = s0 * SQ + pos_s[iq13 + ij1];
            s1 = has2 ? (s1 * SQ + pos_s[iq13 + ij2]) : -1e30f;

            float m = fmaxf(s0, s1);
            #pragma unroll
            for (int o = 16; o; o >>= 1) m = fmaxf(m, __shfl_xor_sync(0xFFFFFFFFu, m, o));
            const float e0 = __expf(s0 - m);
            const float e1 = has2 ? __expf(s1 - m) : 0.f;
            float sum = e0 + e1;
            #pragma unroll
            for (int o = 16; o; o >>= 1) sum += __shfl_xor_sync(0xFFFFFFFFu, sum, o);
            const float inv = __fdividef(1.f, sum);
            const float p0 = e0 * inv;
            const float p1 = e1 * inv;

            float o_acc = 0.f;
            #pragma unroll
            for (int j = 0; j < 32; ++j) {
                const float pj = __shfl_sync(0xFFFFFFFFu, p0, j);
                o_acc = fmaf(pj, vh[j * HDIM + lane], o_acc);
            }
            #pragma unroll
            for (int j = 0; j < 17; ++j) {
                const float pj = __shfl_sync(0xFFFFFFFFu, p1, j);
                o_acc = fmaf(pj, vh[(j + 32) * HDIM + lane], o_acc);
            }

            const int row = base_tok + (qt / WS) * 56 + (qt % WS);
            __nv_bfloat16 oh, ol;
            split2(o_acc, oh, ol);
            g_ah[(size_t)row * CDIM + ch] = oh;
            g_al[(size_t)row * CDIM + ch] = ol;
        }
    }
}

// ------------------------- host launcher -------------------------
extern "C" void kernel_launch(void* const* d_in, const int* in_sizes, int n_in,
                              void* d_out, int out_size)
{
    const float* x     = (const float*)d_in[0];
    const float* pos   = (const float*)d_in[1];
    const float* w_qkv = (const float*)d_in[2];
    const float* b_qkv = (const float*)d_in[3];
    const float* w_out = (const float*)d_in[4];
    const float* b_out = (const float*)d_in[5];
    float* out = (float*)d_out;

    void *p_qkv, *p_xh, *p_xl, *p_ah, *p_al, *p_wqh, *p_wql, *p_woh, *p_wol;
    cudaGetSymbolAddress(&p_qkv, g_qkv);
    cudaGetSymbolAddress(&p_xh,  g_xh);
    cudaGetSymbolAddress(&p_xl,  g_xl);
    cudaGetSymbolAddress(&p_ah,  g_ah);
    cudaGetSymbolAddress(&p_al,  g_al);
    cudaGetSymbolAddress(&p_wqh, g_wqT_h);
    cudaGetSymbolAddress(&p_wql, g_wqT_l);
    cudaGetSymbolAddress(&p_woh, g_woT_h);
    cudaGetSymbolAddress(&p_wol, g_woT_l);

    cudaFuncSetAttribute(gemm_split_kernel, cudaFuncAttributeMaxDynamicSharedMemorySize, GEMM_SMEM);
    cudaFuncSetAttribute(attn_kernel,       cudaFuncAttributeMaxDynamicSharedMemorySize, ATT_SMEM);

    // P0: splits
    split_x_kernel<<<2048, 256>>>(x);
    split_wT_kernel<<<(QKVN * CDIM) / 256, 256>>>(w_qkv, (__nv_bfloat16*)p_wqh, (__nv_bfloat16*)p_wql, QKVN);
    split_wT_kernel<<<(CDIM * CDIM) / 256, 256>>>(w_out, (__nv_bfloat16*)p_woh, (__nv_bfloat16*)p_wol, CDIM);

    // K1: QKV GEMM  [200704 x 768]
    gemm_split_kernel<<<dim3(QKVN / BN, TOK / BM), 256, GEMM_SMEM>>>(
        (const __nv_bfloat16*)p_xh, (const __nv_bfloat16*)p_xl,
        (const __nv_bfloat16*)p_wqh, (const __nv_bfloat16*)p_wql,
        b_qkv, (float*)p_qkv, QKVN);

    // K2: windowed attention (4 CTAs per window, 2 heads each)
    attn_kernel<<<16384, 256, ATT_SMEM>>>(pos);

    // K3: output projection  [200704 x 256]
    gemm_split_kernel<<<dim3(CDIM / BN, TOK / BM), 256, GEMM_SMEM>>>(
        (const __nv_bfloat16*)p_ah, (const __nv_bfloat16*)p_al,
        (const __nv_bfloat16*)p_woh, (const __nv_bfloat16*)p_wol,
        b_out, out, CDIM);
}

// round 17
// speedup vs baseline: 2.1384x; 1.4322x over previous
#include <cuda_runtime.h>
#include <cuda_bf16.h>
#include <cstdint>

#define TOK   200704            // 64*56*56 tokens
#define CDIM  256
#define QKVN  768
#define WS    7
#define WT    49
#define NHEAD 8
#define HDIM  32

// ------------------------- scratch (device globals) -------------------------
__device__ float          g_qkv[154140672];          // [TOK][768] fp32
__device__ __nv_bfloat16  g_xh [51380224];           // [TOK][256] x hi
__device__ __nv_bfloat16  g_xl [51380224];           // [TOK][256] x lo
__device__ __nv_bfloat16  g_ah [51380224];           // attn out hi
__device__ __nv_bfloat16  g_al [51380224];           // attn out lo
__device__ __nv_bfloat16  g_wqT_h[196608];           // WqkvT [768][256] K-major
__device__ __nv_bfloat16  g_wqT_l[196608];
__device__ __nv_bfloat16  g_woT_h[65536];            // WoutT [256][256] K-major
__device__ __nv_bfloat16  g_woT_l[65536];

// ------------------------- helpers -------------------------
__device__ __forceinline__ uint32_t smem_u32(const void* p) {
    uint32_t a;
    asm("{ .reg .u64 t; cvta.to.shared.u64 t, %1; cvt.u32.u64 %0, t; }" : "=r"(a) : "l"(p));
    return a;
}
#define CP_ASYNC16(dst, src) \
    asm volatile("cp.async.cg.shared.global [%0], [%1], 16;\n" :: "r"(dst), "l"(src))
#define CP_COMMIT() asm volatile("cp.async.commit_group;\n" ::: "memory")

__device__ __forceinline__ void ldsm4(uint32_t addr, uint32_t* r) {
    asm volatile("ldmatrix.sync.aligned.m8n8.x4.shared.b16 {%0,%1,%2,%3}, [%4];"
        : "=r"(r[0]), "=r"(r[1]), "=r"(r[2]), "=r"(r[3]) : "r"(addr));
}
__device__ __forceinline__ void mma16816(float* c, const uint32_t* a, const uint32_t* b) {
    asm volatile(
        "mma.sync.aligned.m16n8k16.row.col.f32.bf16.bf16.f32 "
        "{%0,%1,%2,%3}, {%4,%5,%6,%7}, {%8,%9}, {%0,%1,%2,%3};"
        : "+f"(c[0]), "+f"(c[1]), "+f"(c[2]), "+f"(c[3])
        : "r"(a[0]), "r"(a[1]), "r"(a[2]), "r"(a[3]), "r"(b[0]), "r"(b[1]));
}
__device__ __forceinline__ uint32_t sw128(uint32_t row, uint32_t kb) {
    uint32_t off = (row << 7) + kb;
    return off ^ ((off >> 3) & 0x70);
}
__device__ __forceinline__ uint32_t sw64(uint32_t row, uint32_t kb) {
    uint32_t off = (row << 6) + kb;
    return off ^ ((off >> 3) & 0x30);
}
__device__ __forceinline__ void split2(float v, __nv_bfloat16& h, __nv_bfloat16& l) {
    h = __float2bfloat16_rn(v);
    l = __float2bfloat16_rn(v - __bfloat162float(h));
}
// pack two fp32 into bf16 hi/lo split pairs (b16x2 regs)
__device__ __forceinline__ void packsplit2(float v0, float v1, uint32_t& ph, uint32_t& pl) {
    __nv_bfloat16 h0, l0, h1, l1;
    split2(v0, h0, l0); split2(v1, h1, l1);
    __nv_bfloat162 H(h0, h1), L(l0, l1);
    ph = *(uint32_t*)&H; pl = *(uint32_t*)&L;
}

// ------------------------- P0: split kernels -------------------------
__global__ void split_x_kernel(const float* __restrict__ x) {
    size_t n4 = (size_t)TOK * CDIM / 4;
    for (size_t i = (size_t)blockIdx.x * blockDim.x + threadIdx.x; i < n4;
         i += (size_t)gridDim.x * blockDim.x) {
        float4 v = ((const float4*)x)[i];
        __nv_bfloat16 h0,h1,h2,h3,l0,l1,l2,l3;
        split2(v.x,h0,l0); split2(v.y,h1,l1); split2(v.z,h2,l2); split2(v.w,h3,l3);
        ((__nv_bfloat162*)g_xh)[2*i]   = __nv_bfloat162(h0,h1);
        ((__nv_bfloat162*)g_xh)[2*i+1] = __nv_bfloat162(h2,h3);
        ((__nv_bfloat162*)g_xl)[2*i]   = __nv_bfloat162(l0,l1);
        ((__nv_bfloat162*)g_xl)[2*i+1] = __nv_bfloat162(l2,l3);
    }
}
__global__ void split_wT_kernel(const float* __restrict__ w,
                                __nv_bfloat16* __restrict__ oh,
                                __nv_bfloat16* __restrict__ ol, int N) {
    int idx = blockIdx.x * blockDim.x + threadIdx.x;
    if (idx >= N * CDIM) return;
    int n = idx >> 8, k = idx & 255;
    __nv_bfloat16 h, l;
    split2(w[(size_t)k * N + n], h, l);
    oh[(size_t)n * CDIM + k] = h;
    ol[(size_t)n * CDIM + k] = l;
}

// ------------------------- split-bf16 GEMM on mma.sync (R8 proven config) -------------------------
#define BM 128
#define BN 128
#define BK 64
#define NSTAGE 3
#define AH_OFF 0
#define AL_OFF 16384
#define BH_OFF 32768
#define BL_OFF 49152
#define STAGE_BYTES 65536
#define GEMM_SMEM (NSTAGE * STAGE_BYTES)

__device__ __forceinline__ void load_chunk(uint32_t sb, int c,
    const __nv_bfloat16* __restrict__ Ah, const __nv_bfloat16* __restrict__ Al,
    const __nv_bfloat16* __restrict__ Bh, const __nv_bfloat16* __restrict__ Bl,
    int m0, int n0, int tid)
{
    #pragma unroll
    for (int i = 0; i < 4; ++i) {
        int t = tid + i * 256, r = t >> 3, seg = t & 7;
        uint32_t dst = sb + sw128(r, seg * 16);
        size_t ga = (size_t)(m0 + r) * CDIM + c * BK + seg * 8;
        CP_ASYNC16(dst + AH_OFF, Ah + ga);
        CP_ASYNC16(dst + AL_OFF, Al + ga);
        size_t gb = (size_t)(n0 + r) * CDIM + c * BK + seg * 8;
        CP_ASYNC16(dst + BH_OFF, Bh + gb);
        CP_ASYNC16(dst + BL_OFF, Bl + gb);
    }
    CP_COMMIT();
}

__global__ __launch_bounds__(256, 1)
void gemm_split_kernel(const __nv_bfloat16* __restrict__ Ah, const __nv_bfloat16* __restrict__ Al,
                       const __nv_bfloat16* __restrict__ Bh, const __nv_bfloat16* __restrict__ Bl,
                       const float* __restrict__ bias, float* __restrict__ outp, int out_ld)
{
    extern __shared__ __align__(1024) char smem[];
    const uint32_t smb = smem_u32(smem);
    const int tid  = threadIdx.x;
    const int lane = tid & 31, wid = tid >> 5;
    const int wm = wid & 3, wn = wid >> 2;
    const int n0 = blockIdx.x * BN;
    const int m0 = blockIdx.y * BM;

    const int li = lane & 7, lg = lane >> 3;
    const int aRowOff = ((lg & 1) << 3) + li;
    const int aKoff   = (lg >> 1) << 4;
    const int bRowOff = ((lg >> 1) << 3) + li;
    const int bKoff   = (lg & 1) << 4;

    float acc[2][8][4];
    #pragma unroll
    for (int a = 0; a < 2; ++a)
        #pragma unroll
        for (int b = 0; b < 8; ++b)
            #pragma unroll
            for (int cc = 0; cc < 4; ++cc) acc[a][b][cc] = 0.f;

    load_chunk(smb + 0 * STAGE_BYTES, 0, Ah, Al, Bh, Bl, m0, n0, tid);
    load_chunk(smb + 1 * STAGE_BYTES, 1, Ah, Al, Bh, Bl, m0, n0, tid);

    #pragma unroll 1
    for (int c = 0; c < 4; ++c) {
        if (c < 3) asm volatile("cp.async.wait_group 1;\n" ::: "memory");
        else       asm volatile("cp.async.wait_group 0;\n" ::: "memory");
        __syncthreads();
        const uint32_t sb = smb + (uint32_t)(c % NSTAGE) * STAGE_BYTES;

        #pragma unroll
        for (int s = 0; s < 4; ++s) {
            const uint32_t kbA = (uint32_t)(s * 32 + aKoff);
            const uint32_t kbB = (uint32_t)(s * 32 + bKoff);
            uint32_t ah[2][4], al[2][4];
            #pragma unroll
            for (int mt = 0; mt < 2; ++mt) {
                const uint32_t arow = (uint32_t)(wm * 32 + mt * 16 + aRowOff);
                const uint32_t sw = sw128(arow, kbA);
                ldsm4(sb + AH_OFF + sw, ah[mt]);
                ldsm4(sb + AL_OFF + sw, al[mt]);
            }
            uint32_t bh[4][4], bl[4][4];
            #pragma unroll
            for (int nt = 0; nt < 4; ++nt) {
                const uint32_t brow = (uint32_t)(wn * 64 + nt * 16 + bRowOff);
                const uint32_t sw = sw128(brow, kbB);
                ldsm4(sb + BH_OFF + sw, bh[nt]);
                ldsm4(sb + BL_OFF + sw, bl[nt]);
            }
            #pragma unroll
            for (int mt = 0; mt < 2; ++mt)
                #pragma unroll
                for (int nt = 0; nt < 4; ++nt) {
                    mma16816(acc[mt][nt*2],   ah[mt], &bh[nt][0]);
                    mma16816(acc[mt][nt*2],   ah[mt], &bl[nt][0]);
                    mma16816(acc[mt][nt*2],   al[mt], &bh[nt][0]);
                    mma16816(acc[mt][nt*2+1], ah[mt], &bh[nt][2]);
                    mma16816(acc[mt][nt*2+1], ah[mt], &bl[nt][2]);
                    mma16816(acc[mt][nt*2+1], al[mt], &bh[nt][2]);
                }
        }
        if (c + 2 < 4)
            load_chunk(smb + (uint32_t)((c + 2) % NSTAGE) * STAGE_BYTES, c + 2,
                       Ah, Al, Bh, Bl, m0, n0, tid);
    }

    #pragma unroll
    for (int mt = 0; mt < 2; ++mt) {
        const int row = m0 + wm * 32 + mt * 16 + (lane >> 2);
        #pragma unroll
        for (int nt = 0; nt < 8; ++nt) {
            const int col = n0 + wn * 64 + nt * 8 + 2 * (lane & 3);
            const float b0 = __ldg(bias + col), b1 = __ldg(bias + col + 1);
            float2 v0 = make_float2(acc[mt][nt][0] + b0, acc[mt][nt][1] + b1);
            float2 v1 = make_float2(acc[mt][nt][2] + b0, acc[mt][nt][3] + b1);
            *(float2*)(outp + (size_t)row * out_ld + col)       = v0;
            *(float2*)(outp + (size_t)(row + 8) * out_ld + col) = v1;
        }
    }
}

// ------------------------- K2: windowed attention on mma.sync -------------------------
// 1 CTA per window, 8 warps = 8 heads. Per head:
//   Q[64pad][32] bf16 h/l (sw64 rows), K[64pad][32] h/l (sw64), vT[32][64pad] h/l (sw128)
//   S = Q@K^T (split, 3 terms) -> in-register softmax on fragments -> P (split) -> O = P@V (3 terms)
#define AQH 0
#define AQL 32768
#define AKH 65536
#define AKL 98304
#define AVH 131072
#define AVL 163840
#define APOS 196608
#define ATT_SMEM (APOS + 1024)

__global__ __launch_bounds__(256, 1)
void attn_mma_kernel(const float* __restrict__ pos)
{
    extern __shared__ __align__(1024) char smem[];
    const uint32_t smb = smem_u32(smem);
    float* pos_s = (float*)(smem + APOS);

    const int tid  = threadIdx.x;
    const int lane = tid & 31;
    const int wid  = tid >> 5;
    const int win  = blockIdx.x;
    const int b = win >> 6, wi = (win >> 3) & 7, wj = win & 7;
    const int base_tok = b * 3136 + (wi * WS) * 56 + wj * WS;

    // ---- zero K and V regions (pad rows MUST be 0) ----
    {
        uint4 z = make_uint4(0,0,0,0);
        uint4* p = (uint4*)(smem + AKH);
        #pragma unroll
        for (int i = 0; i < 32; ++i) p[tid + i * 256] = z;   // 131072 bytes
    }
    if (tid < 169) pos_s[tid] = pos[tid];
    __syncthreads();

    // ---- load + split qkv into smem ----
    {
        // Q (tid<128) / K (tid>=128): thread -> head h=(c>>4), d-pair dp=(c&15)
        const int c  = tid & 127;
        const int h  = c >> 4, dp = c & 15;
        const int go = ((tid < 128) ? 0 : 256) + h * 32 + dp * 2;
        const uint32_t baseH = ((tid < 128) ? AQH : AKH) + (uint32_t)h * 4096;
        #pragma unroll
        for (int t = 0; t < WT; ++t) {
            const int row = base_tok + (t / WS) * 56 + (t % WS);
            const float2 v = *(const float2*)(g_qkv + (size_t)row * QKVN + go);
            __nv_bfloat16 h0,l0,h1,l1;
            split2(v.x, h0, l0); split2(v.y, h1, l1);
            const uint32_t off = baseH + sw64((uint32_t)t, (uint32_t)(dp * 4));
            *(__nv_bfloat162*)(smem + off)         = __nv_bfloat162(h0, h1);
            *(__nv_bfloat162*)(smem + off + 32768) = __nv_bfloat162(l0, l1);
        }
        // V transposed: warp = head, lane = d
        const int hv = wid, d = lane;
        const uint32_t vbase = AVH + (uint32_t)hv * 4096;
        #pragma unroll
        for (int t = 0; t < WT; ++t) {
            const int row = base_tok + (t / WS) * 56 + (t % WS);
            const float v = g_qkv[(size_t)row * QKVN + 512 + hv * 32 + d];
            __nv_bfloat16 vh, vl;
            split2(v, vh, vl);
            const uint32_t off = vbase + sw128((uint32_t)d, (uint32_t)(t * 2));
            *(__nv_bfloat16*)(smem + off)         = vh;
            *(__nv_bfloat16*)(smem + off + 32768) = vl;
        }
    }
    __syncthreads();

    // ---- per-head attention (warp = head) ----
    const int h = wid;
    const int li = lane & 7, lg = lane >> 3;
    const int aRowOff = ((lg & 1) << 3) + li;
    const int aKoff   = (lg >> 1) << 4;
    const int bRowOff = ((lg >> 1) << 3) + li;
    const int bKoff   = (lg & 1) << 4;

    const uint32_t QHh = smb + AQH + (uint32_t)h * 4096;
    const uint32_t KHh = smb + AKH + (uint32_t)h * 4096;
    const uint32_t VHh = smb + AVH + (uint32_t)h * 4096;
    const float SQ = 5.6568542494923806f;       // sqrt(32), reference multiplies

    #pragma unroll 1
    for (int mt = 0; mt < 4; ++mt) {
        // ---------- S = Q K^T ----------
        float sf[8][4];
        #pragma unroll
        for (int j = 0; j < 8; ++j)
            #pragma unroll
            for (int cc = 0; cc < 4; ++cc) sf[j][cc] = 0.f;

        #pragma unroll
        for (int ks = 0; ks < 2; ++ks) {
            uint32_t qh4[4], ql4[4];
            const uint32_t aoff = sw64((uint32_t)(mt * 16 + aRowOff), (uint32_t)(ks * 32 + aKoff));
            ldsm4(QHh + aoff, qh4);
            ldsm4(QHh + aoff + 32768, ql4);
            #pragma unroll
            for (int ntp = 0; ntp < 4; ++ntp) {
                uint32_t kh4[4], kl4[4];
                const uint32_t boff = sw64((uint32_t)(ntp * 16 + bRowOff), (uint32_t)(ks * 32 + bKoff));
                ldsm4(KHh + boff, kh4);
                ldsm4(KHh + boff + 32768, kl4);
                mma16816(sf[ntp*2],   qh4, &kh4[0]);
                mma16816(sf[ntp*2],   qh4, &kl4[0]);
                mma16816(sf[ntp*2],   ql4, &kh4[0]);
                mma16816(sf[ntp*2+1], qh4, &kh4[2]);
                mma16816(sf[ntp*2+1], qh4, &kl4[2]);
                mma16816(sf[ntp*2+1], ql4, &kh4[2]);
            }
        }

        // ---------- bias + mask + softmax on fragments ----------
        const int r0 = mt * 16 + (lane >> 2), r1 = r0 + 8;
        const int iqa = (r0 < WT) ? (r0 / WS + r0 % WS) * 13 : 0;
        const int iqb = (r1 < WT) ? (r1 / WS + r1 % WS) * 13 : 0;
        float m0 = -1e30f, m1 = -1e30f;
        #pragma unroll
        for (int j = 0; j < 8; ++j) {
            const int c0 = j * 8 + 2 * (lane & 3), c1 = c0 + 1;
            const bool v0 = (c0 < WT), v1 = (c1 < WT);
            const int ij0 = v0 ? (c0 / WS + c0 % WS) : 0;
            const int ij1 = v1 ? (c1 / WS + c1 % WS) : 0;
            sf[j][0] = v0 ? fmaf(sf[j][0], SQ, pos_s[iqa + ij0]) : -1e30f;
            sf[j][1] = v1 ? fmaf(sf[j][1], SQ, pos_s[iqa + ij1]) : -1e30f;
            sf[j][2] = v0 ? fmaf(sf[j][2], SQ, pos_s[iqb + ij0]) : -1e30f;
            sf[j][3] = v1 ? fmaf(sf[j][3], SQ, pos_s[iqb + ij1]) : -1e30f;
            m0 = fmaxf(m0, fmaxf(sf[j][0], sf[j][1]));
            m1 = fmaxf(m1, fmaxf(sf[j][2], sf[j][3]));
        }
        m0 = fmaxf(m0, __shfl_xor_sync(0xFFFFFFFFu, m0, 1));
        m1 = fmaxf(m1, __shfl_xor_sync(0xFFFFFFFFu, m1, 1));
        m0 = fmaxf(m0, __shfl_xor_sync(0xFFFFFFFFu, m0, 2));
        m1 = fmaxf(m1, __shfl_xor_sync(0xFFFFFFFFu, m1, 2));

        float l0 = 0.f, l1 = 0.f;
        #pragma unroll
        for (int j = 0; j < 8; ++j) {
            sf[j][0] = __expf(sf[j][0] - m0);
            sf[j][1] = __expf(sf[j][1] - m0);
            sf[j][2] = __expf(sf[j][2] - m1);
            sf[j][3] = __expf(sf[j][3] - m1);
            l0 += sf[j][0] + sf[j][1];
            l1 += sf[j][2] + sf[j][3];
        }
        l0 += __shfl_xor_sync(0xFFFFFFFFu, l0, 1);
        l1 += __shfl_xor_sync(0xFFFFFFFFu, l1, 1);
        l0 += __shfl_xor_sync(0xFFFFFFFFu, l0, 2);
        l1 += __shfl_xor_sync(0xFFFFFFFFu, l1, 2);

        // ---------- P fragments (split bf16), accum layout == A-frag layout ----------
        uint32_t pa[4][4], pla[4][4];
        #pragma unroll
        for (int kt = 0; kt < 4; ++kt) {
            packsplit2(sf[2*kt][0],   sf[2*kt][1],   pa[kt][0], pla[kt][0]);
            packsplit2(sf[2*kt][2],   sf[2*kt][3],   pa[kt][1], pla[kt][1]);
            packsplit2(sf[2*kt+1][0], sf[2*kt+1][1], pa[kt][2], pla[kt][2]);
            packsplit2(sf[2*kt+1][2], sf[2*kt+1][3], pa[kt][3], pla[kt][3]);
        }

        // ---------- O = P V ----------
        float of[4][4];
        #pragma unroll
        for (int nt = 0; nt < 4; ++nt)
            #pragma unroll
            for (int cc = 0; cc < 4; ++cc) of[nt][cc] = 0.f;

        #pragma unroll
        for (int kt = 0; kt < 4; ++kt) {
            #pragma unroll
            for (int vp = 0; vp < 2; ++vp) {
                uint32_t vh4[4], vl4[4];
                const uint32_t voff = sw128((uint32_t)(vp * 16 + bRowOff), (uint32_t)(kt * 32 + bKoff));
                ldsm4(VHh + voff, vh4);
                ldsm4(VHh + voff + 32768, vl4);
                mma16816(of[vp*2],   pa[kt],  &vh4[0]);
                mma16816(of[vp*2],   pa[kt],  &vl4[0]);
                mma16816(of[vp*2],   pla[kt], &vh4[0]);
                mma16816(of[vp*2+1], pa[kt],  &vh4[2]);
                mma16816(of[vp*2+1], pa[kt],  &vl4[2]);
                mma16816(of[vp*2+1], pla[kt], &vh4[2]);
            }
        }

        // ---------- epilogue: normalize by l, split, store ----------
        const float linv0 = __fdividef(1.f, l0);
        const float linv1 = __fdividef(1.f, l1);
        const bool ok0 = (r0 < WT), ok1 = (r1 < WT);
        const int tok0 = ok0 ? (base_tok + (r0 / WS) * 56 + (r0 % WS)) : 0;
        const int tok1 = ok1 ? (base_tok + (r1 / WS) * 56 + (r1 % WS)) : 0;
        #pragma unroll
        for (int nt = 0; nt < 4; ++nt) {
            const int dcol = nt * 8 + 2 * (lane & 3);
            const int ch = h * HDIM + dcol;
            if (ok0) {
                __nv_bfloat16 h0,l0b,h1,l1b;
                split2(of[nt][0] * linv0, h0, l0b);
                split2(of[nt][1] * linv0, h1, l1b);
                const size_t e = ((size_t)tok0 * CDIM + ch) >> 1;
                ((__nv_bfloat162*)g_ah)[e] = __nv_bfloat162(h0, h1);
                ((__nv_bfloat162*)g_al)[e] = __nv_bfloat162(l0b, l1b);
            }
            if (ok1) {
                __nv_bfloat16 h0,l0b,h1,l1b;
                split2(of[nt][2] * linv1, h0, l0b);
                split2(of[nt][3] * linv1, h1, l1b);
                const size_t e = ((size_t)tok1 * CDIM + ch) >> 1;
                ((__nv_bfloat162*)g_ah)[e] = __nv_bfloat162(h0, h1);
                ((__nv_bfloat162*)g_al)[e] = __nv_bfloat162(l0b, l1b);
            }
        }
    }
}

// ------------------------- host launcher -------------------------
extern "C" void kernel_launch(void* const* d_in, const int* in_sizes, int n_in,
                              void* d_out, int out_size)
{
    const float* x     = (const float*)d_in[0];
    const float* pos   = (const float*)d_in[1];
    const float* w_qkv = (const float*)d_in[2];
    const float* b_qkv = (const float*)d_in[3];
    const float* w_out = (const float*)d_in[4];
    const float* b_out = (const float*)d_in[5];
    float* out = (float*)d_out;

    void *p_qkv, *p_xh, *p_xl, *p_ah, *p_al, *p_wqh, *p_wql, *p_woh, *p_wol;
    cudaGetSymbolAddress(&p_qkv, g_qkv);
    cudaGetSymbolAddress(&p_xh,  g_xh);
    cudaGetSymbolAddress(&p_xl,  g_xl);
    cudaGetSymbolAddress(&p_ah,  g_ah);
    cudaGetSymbolAddress(&p_al,  g_al);
    cudaGetSymbolAddress(&p_wqh, g_wqT_h);
    cudaGetSymbolAddress(&p_wql, g_wqT_l);
    cudaGetSymbolAddress(&p_woh, g_woT_h);
    cudaGetSymbolAddress(&p_wol, g_woT_l);

    cudaFuncSetAttribute(gemm_split_kernel, cudaFuncAttributeMaxDynamicSharedMemorySize, GEMM_SMEM);
    cudaFuncSetAttribute(attn_mma_kernel,   cudaFuncAttributeMaxDynamicSharedMemorySize, ATT_SMEM);

    // P0: splits
    split_x_kernel<<<2048, 256>>>(x);
    split_wT_kernel<<<(QKVN * CDIM) / 256, 256>>>(w_qkv, (__nv_bfloat16*)p_wqh, (__nv_bfloat16*)p_wql, QKVN);
    split_wT_kernel<<<(CDIM * CDIM) / 256, 256>>>(w_out, (__nv_bfloat16*)p_woh, (__nv_bfloat16*)p_wol, CDIM);

    // K1: QKV GEMM  [200704 x 768]
    gemm_split_kernel<<<dim3(QKVN / BN, TOK / BM), 256, GEMM_SMEM>>>(
        (const __nv_bfloat16*)p_xh, (const __nv_bfloat16*)p_xl,
        (const __nv_bfloat16*)p_wqh, (const __nv_bfloat16*)p_wql,
        b_qkv, (float*)p_qkv, QKVN);

    // K2: windowed attention on tensor cores (1 CTA per window)
    attn_mma_kernel<<<4096, 256, ATT_SMEM>>>(pos);

    // K3: output projection  [200704 x 256]
    gemm_split_kernel<<<dim3(CDIM / BN, TOK / BM), 256, GEMM_SMEM>>>(
        (const __nv_bfloat16*)p_ah, (const __nv_bfloat16*)p_al,
        (const __nv_bfloat16*)p_woh, (const __nv_bfloat16*)p_wol,
        b_out, out, CDIM);
}